// round 15
// baseline (speedup 1.0000x reference)
#include <cuda_runtime.h>
#include <cuda_fp16.h>
#include <mma.h>
#include <math.h>
#include <cstdint>

using namespace nvcuda;

#define SEQ 12
#define D 1024
#define H 16
#define HD 64
#define BATCH 4096
#define NROWS (BATCH * SEQ)   // 49152
#define EPS 1e-5f

// ---------------- scratch (no allocations allowed) ----------------
__device__ float  g_proj[NROWS * D];
__device__ __half g_xh[NROWS * D];     // fp16 x
__device__ __half g_atth[NROWS * D];   // fp16 attention output
__device__ __half g_wq[D * D];         // fp16 weights (original [K,N] layout)
__device__ __half g_wk[D * D];
__device__ __half g_wv[D * D];
__device__ __half g_wo[D * D];
__device__ float  g_mask[SEQ * SEQ];

// ---------------- edge mask (dtype-sniffing: int32 vs int64 payload) ----------------
__global__ void mask_kernel(const int* __restrict__ e32, int n_elems) {
    __shared__ int is64;
    int tid = threadIdx.x;
    if (tid == 0) {
        int all_odd_zero = 1;
        for (int i = 1; i < n_elems; i += 2)
            if (e32[i] != 0) { all_odd_zero = 0; break; }
        is64 = all_odd_zero;
    }
    if (tid < SEQ * SEQ) g_mask[tid] = 0.0f;
    __syncthreads();
    int n_edges = n_elems / 2;
    for (int t = tid; t < n_edges; t += blockDim.x) {
        int r, c;
        if (is64) { r = e32[4 * t]; c = e32[4 * t + 2]; }
        else      { r = e32[2 * t]; c = e32[2 * t + 1]; }
        if (r >= 0 && r < SEQ && c >= 0 && c < SEQ)
            g_mask[r * SEQ + c] = 1.0f;
    }
}

// ---------------- fp32 -> fp16 conversion (vectorized) ----------------
union H2U2 { __half2 h[2]; uint2 u; };

__global__ void __launch_bounds__(256) round_half(const float* __restrict__ in,
                                                  __half* __restrict__ out, int n4) {
    int i = blockIdx.x * blockDim.x + threadIdx.x;
    if (i < n4) {
        float4 v = ((const float4*)in)[i];
        H2U2 t;
        t.h[0] = __floats2half2_rn(v.x, v.y);
        t.h[1] = __floats2half2_rn(v.z, v.w);
        ((uint2*)out)[i] = t.u;
    }
}

__global__ void __launch_bounds__(256) round_w4(const float* __restrict__ w0,
                                                const float* __restrict__ w1,
                                                const float* __restrict__ w2,
                                                const float* __restrict__ w3,
                                                __half* __restrict__ o0,
                                                __half* __restrict__ o1,
                                                __half* __restrict__ o2,
                                                __half* __restrict__ o3, int n4) {
    const float* in; __half* out;
    switch (blockIdx.y) {
        case 0: in = w0; out = o0; break;
        case 1: in = w1; out = o1; break;
        case 2: in = w2; out = o2; break;
        default: in = w3; out = o3; break;
    }
    int i = blockIdx.x * blockDim.x + threadIdx.x;
    if (i < n4) {
        float4 v = ((const float4*)in)[i];
        H2U2 t;
        t.h[0] = __floats2half2_rn(v.x, v.y);
        t.h[1] = __floats2half2_rn(v.z, v.w);
        ((uint2*)out)[i] = t.u;
    }
}

// ---------------- cp.async helpers ----------------
__device__ __forceinline__ void cp16(void* smem_dst, const void* gmem_src) {
    unsigned int d = (unsigned int)__cvta_generic_to_shared(smem_dst);
    asm volatile("cp.async.cg.shared.global [%0], [%1], 16;\n" :: "r"(d), "l"(gmem_src));
}
__device__ __forceinline__ void cp_commit() { asm volatile("cp.async.commit_group;\n"); }
template <int N>
__device__ __forceinline__ void cp_wait() { asm volatile("cp.async.wait_group %0;\n" :: "n"(N)); }

// ================= fused QKV GEMM + masked attention =================
// CTA: 96 rows (8 batches) x 192 cols ([Q|K|V] of ONE head), K=1024.
// Grid (16 heads, 512 rowblocks) — x fastest => 16 head-CTAs share A block in L2.
// 256 threads, 8 warps (2x4), warp tile 48x48. 3-stage cp.async pipeline.
// Epilogue: stage fp32 QKV in pipeline smem, per-warp attention (warp = batch).
#define FBM 96
#define FBN 192
#define FBK 64
#define F_LDA 72             // halfs
#define F_LDB 200            // halfs
#define F_SA (FBM * F_LDA)   // 6912 halfs
#define F_SB (FBK * F_LDB)   // 12800 halfs
#define F_STAGES 3
#define F_SMEM ((F_STAGES * (F_SA + F_SB)) * 2)  // 118,272 bytes
#define F_STG 200            // epilogue staging stride (floats)

__global__ void __launch_bounds__(256, 1) qkv_attn(const __half* __restrict__ A,
                                                   const __half* __restrict__ Wq,
                                                   const __half* __restrict__ Wk,
                                                   const __half* __restrict__ Wv,
                                                   const float* __restrict__ bq,
                                                   const float* __restrict__ bk,
                                                   const float* __restrict__ bv) {
    extern __shared__ __half smh[];
    __half* As = smh;
    __half* Bs = smh + F_STAGES * F_SA;

    const int tid = threadIdx.x;
    const int wid = tid >> 5;
    const int lane = tid & 31;
    const int wm  = wid >> 2;        // 0..1 -> 48 rows
    const int wn  = wid & 3;         // 0..3 -> 48 cols
    const int h = blockIdx.x;        // head
    const long brow = (long)blockIdx.y * FBM;

    wmma::fragment<wmma::accumulator, 16, 16, 16, float> acc[3][3];
    #pragma unroll
    for (int m = 0; m < 3; m++)
        #pragma unroll
        for (int n = 0; n < 3; n++)
            wmma::fill_fragment(acc[m][n], 0.0f);

    const int ktiles = D / FBK;      // 16

    auto issue = [&](int kt, int buf) {
        __half* ad = As + buf * F_SA;
        const __half* Ag = A + brow * D + kt * FBK;
        #pragma unroll
        for (int i = 0; i < 3; i++) {
            int idx = tid + i * 256;          // 0..767
            int r  = idx >> 3;                // 0..95
            int c8 = (idx & 7) << 3;          // 0..56
            cp16(ad + r * F_LDA + c8, Ag + (long)r * D + c8);
        }
        __half* bd = Bs + buf * F_SB;
        #pragma unroll
        for (int i = 0; i < 6; i++) {
            int idx = tid + i * 256;          // 0..1535
            int r  = idx / 24;                // 0..63 (k row)
            int cc = idx - r * 24;            // 0..23
            int sel = cc >> 3;                // 0..2 : Q,K,V
            int c8 = (cc & 7) << 3;           // 0..56
            const __half* W = (sel == 0) ? Wq : ((sel == 1) ? Wk : Wv);
            cp16(bd + r * F_LDB + sel * 64 + c8,
                 W + (long)(kt * FBK + r) * D + h * HD + c8);
        }
    };

    issue(0, 0); cp_commit();
    issue(1, 1); cp_commit();

    for (int kt = 0; kt < ktiles; kt++) {
        cp_wait<1>();
        __syncthreads();

        if (kt + 2 < ktiles) issue(kt + 2, (kt + 2) % F_STAGES);
        cp_commit();

        const __half* a = As + (kt % F_STAGES) * F_SA;
        const __half* b = Bs + (kt % F_STAGES) * F_SB;
        #pragma unroll
        for (int ks = 0; ks < 4; ks++) {
            const int k0 = ks * 16;
            wmma::fragment<wmma::matrix_a, 16, 16, 16, __half, wmma::row_major> af[3];
            wmma::fragment<wmma::matrix_b, 16, 16, 16, __half, wmma::row_major> bf[3];
            #pragma unroll
            for (int m = 0; m < 3; m++)
                wmma::load_matrix_sync(af[m], a + (wm * 48 + m * 16) * F_LDA + k0, F_LDA);
            #pragma unroll
            for (int n = 0; n < 3; n++)
                wmma::load_matrix_sync(bf[n], b + k0 * F_LDB + wn * 48 + n * 16, F_LDB);
            #pragma unroll
            for (int m = 0; m < 3; m++)
                #pragma unroll
                for (int n = 0; n < 3; n++)
                    wmma::mma_sync(acc[m][n], af[m], bf[n], acc[m][n]);
        }
    }

    // ---------- epilogue: stage fp32 QKV, then per-warp attention ----------
    cp_wait<0>();
    __syncthreads();
    float* stage = (float*)smh;                 // [96][F_STG] = 76,800 B
    float* scb   = stage + FBM * F_STG;         // 8 * 144 floats
    float* mk    = scb + 8 * 144;               // 144 floats

    #pragma unroll
    for (int m = 0; m < 3; m++)
        #pragma unroll
        for (int n = 0; n < 3; n++)
            wmma::store_matrix_sync(stage + (wm * 48 + m * 16) * F_STG + wn * 48 + n * 16,
                                    acc[m][n], F_STG, wmma::mem_row_major);
    if (tid < SEQ * SEQ) mk[tid] = g_mask[tid];
    __syncthreads();

    // warp wid owns batch rows [wid*12, wid*12+12)
    const int r0 = wid * SEQ;
    float* sc = scb + wid * 144;

    const float2 bq2 = ((const float2*)(bq + h * HD))[lane];
    const float2 bk2 = ((const float2*)(bk + h * HD))[lane];
    const float2 bv2 = ((const float2*)(bv + h * HD))[lane];

    #pragma unroll
    for (int s = 0; s < SEQ; s++) {
        float* row = stage + (r0 + s) * F_STG;
        row[2 * lane]           += bq2.x;
        row[2 * lane + 1]       += bq2.y;
        row[64 + 2 * lane]      += bk2.x;
        row[64 + 2 * lane + 1]  += bk2.y;
        row[128 + 2 * lane]     += bv2.x;
        row[128 + 2 * lane + 1] += bv2.y;
    }
    __syncwarp();

    // scores (144 over 32 lanes)
    #pragma unroll
    for (int it = 0; it < 5; it++) {
        int t = lane + it * 32;
        if (t < SEQ * SEQ) {
            int i = t / SEQ, j = t - (t / SEQ) * SEQ;
            const float* qr = stage + (r0 + i) * F_STG;
            const float* kr = stage + (r0 + j) * F_STG + 64;
            float s = 0.0f;
            #pragma unroll
            for (int d = 0; d < HD; d++) s += qr[d] * kr[d];
            sc[t] = (mk[t] == 0.0f) ? -INFINITY : s * 0.125f;
        }
    }
    __syncwarp();

    if (lane < SEQ) {
        float mx = -INFINITY;
        #pragma unroll
        for (int j = 0; j < SEQ; j++) mx = fmaxf(mx, sc[lane * SEQ + j]);
        float sum = 0.0f;
        #pragma unroll
        for (int j = 0; j < SEQ; j++) {
            float e = __expf(sc[lane * SEQ + j] - mx);
            sc[lane * SEQ + j] = e;
            sum += e;
        }
        float inv = 1.0f / sum;
        #pragma unroll
        for (int j = 0; j < SEQ; j++) sc[lane * SEQ + j] *= inv;
    }
    __syncwarp();

    #pragma unroll
    for (int s = 0; s < SEQ; s++) {
        float a0 = 0.0f, a1 = 0.0f;
        #pragma unroll
        for (int j = 0; j < SEQ; j++) {
            float p = sc[s * SEQ + j];
            const float* vr = stage + (r0 + j) * F_STG + 128;
            a0 += p * vr[2 * lane];
            a1 += p * vr[2 * lane + 1];
        }
        long grow = brow + r0 + s;
        ((__half2*)g_atth)[(grow * D + h * HD) / 2 + lane] = __floats2half2_rn(a0, a1);
    }
}

// ---------------- pipelined FP16 GEMM, fp32 out (Wo projection) ----------------
#define BM 128
#define BN 128
#define BK 64
#define LDA_H 72
#define LDB_H 136
#define SA_H (BM * LDA_H)
#define SB_H (BK * LDB_H)
#define STAGES 3
#define GEMM_SMEM ((STAGES * (SA_H + SB_H)) * 2)   // 107,520 bytes

__global__ void __launch_bounds__(128, 2) gemm_fp16(const __half* __restrict__ A,
                                                    const __half* __restrict__ B,
                                                    float* __restrict__ C,
                                                    int M, int N, int K) {
    extern __shared__ __half smh[];
    __half* As = smh;
    __half* Bs = smh + STAGES * SA_H;

    const int tid = threadIdx.x;
    const int wid = tid >> 5;
    const int wm  = wid >> 1;
    const int wn  = wid & 1;
    const long brow = (long)blockIdx.y * BM;
    const long bcol = (long)blockIdx.x * BN;

    wmma::fragment<wmma::accumulator, 16, 16, 16, float> acc[4][4];
    #pragma unroll
    for (int m = 0; m < 4; m++)
        #pragma unroll
        for (int n = 0; n < 4; n++)
            wmma::fill_fragment(acc[m][n], 0.0f);

    const int ktiles = K / BK;

    auto issue = [&](int kt, int buf) {
        __half* ad = As + buf * SA_H;
        const __half* Ag = A + brow * K + (long)kt * BK;
        #pragma unroll
        for (int i = 0; i < 8; i++) {
            int idx = tid + i * 128;
            int r  = idx >> 3;
            int c8 = (idx & 7) << 3;
            cp16(ad + r * LDA_H + c8, Ag + (long)r * K + c8);
        }
        __half* bd = Bs + buf * SB_H;
        const __half* Bg = B + (long)kt * BK * N + bcol;
        #pragma unroll
        for (int i = 0; i < 8; i++) {
            int idx = tid + i * 128;
            int r  = idx >> 4;
            int c8 = (idx & 15) << 3;
            cp16(bd + r * LDB_H + c8, Bg + (long)r * N + c8);
        }
    };

    issue(0, 0); cp_commit();
    issue(1, 1); cp_commit();

    for (int kt = 0; kt < ktiles; kt++) {
        cp_wait<1>();
        __syncthreads();

        if (kt + 2 < ktiles) issue(kt + 2, (kt + 2) % STAGES);
        cp_commit();

        const __half* a = As + (kt % STAGES) * SA_H;
        const __half* b = Bs + (kt % STAGES) * SB_H;
        #pragma unroll
        for (int ks = 0; ks < 4; ks++) {
            const int k0 = ks * 16;
            wmma::fragment<wmma::matrix_a, 16, 16, 16, __half, wmma::row_major> af[4];
            wmma::fragment<wmma::matrix_b, 16, 16, 16, __half, wmma::row_major> bf[4];
            #pragma unroll
            for (int m = 0; m < 4; m++)
                wmma::load_matrix_sync(af[m], a + (wm * 64 + m * 16) * LDA_H + k0, LDA_H);
            #pragma unroll
            for (int n = 0; n < 4; n++)
                wmma::load_matrix_sync(bf[n], b + k0 * LDB_H + wn * 64 + n * 16, LDB_H);
            #pragma unroll
            for (int m = 0; m < 4; m++)
                #pragma unroll
                for (int n = 0; n < 4; n++)
                    wmma::mma_sync(acc[m][n], af[m], bf[n], acc[m][n]);
        }
    }

    #pragma unroll
    for (int m = 0; m < 4; m++)
        #pragma unroll
        for (int n = 0; n < 4; n++) {
            float* cp = C + (brow + wm * 64 + m * 16) * N + bcol + wn * 64 + n * 16;
            wmma::store_matrix_sync(cp, acc[m][n], N, wmma::mem_row_major);
        }
}

// ---------------- bias + residual + LayerNorm (single-pass, float4) ----------------
__global__ void __launch_bounds__(256) ln_kernel(const float* __restrict__ x,
                                                 const float* __restrict__ bo,
                                                 const float* __restrict__ gamma,
                                                 const float* __restrict__ beta,
                                                 float* __restrict__ out) {
    const int row = blockIdx.x;
    const float4* p4  = (const float4*)(g_proj + (long)row * D);
    const float4* x4  = (const float4*)(x + (long)row * D);
    const int tid = threadIdx.x;
    const int lane = tid & 31, w = tid >> 5;
    __shared__ float rs[8], rq[8];

    float4 pv = p4[tid];
    float4 xv = x4[tid];
    float4 bv = ((const float4*)bo)[tid];
    float4 hv;
    hv.x = pv.x + bv.x + xv.x;
    hv.y = pv.y + bv.y + xv.y;
    hv.z = pv.z + bv.z + xv.z;
    hv.w = pv.w + bv.w + xv.w;

    float sum = hv.x + hv.y + hv.z + hv.w;
    float sq  = hv.x * hv.x + hv.y * hv.y + hv.z * hv.z + hv.w * hv.w;
    #pragma unroll
    for (int o = 16; o; o >>= 1) {
        sum += __shfl_xor_sync(~0u, sum, o);
        sq  += __shfl_xor_sync(~0u, sq, o);
    }
    if (lane == 0) { rs[w] = sum; rq[w] = sq; }
    __syncthreads();
    if (w == 0) {
        float s = (lane < 8) ? rs[lane] : 0.0f;
        float q = (lane < 8) ? rq[lane] : 0.0f;
        #pragma unroll
        for (int o = 4; o; o >>= 1) {
            s += __shfl_xor_sync(~0u, s, o);
            q += __shfl_xor_sync(~0u, q, o);
        }
        if (lane == 0) { rs[0] = s; rq[0] = q; }
    }
    __syncthreads();
    const float mu  = rs[0] * (1.0f / D);
    const float var = rq[0] * (1.0f / D) - mu * mu;
    const float inv = rsqrtf(var + EPS);

    float4 gv = ((const float4*)gamma)[tid];
    float4 bt = ((const float4*)beta)[tid];
    float4 ov;
    ov.x = (hv.x - mu) * inv * gv.x + bt.x;
    ov.y = (hv.y - mu) * inv * gv.y + bt.y;
    ov.z = (hv.z - mu) * inv * gv.z + bt.z;
    ov.w = (hv.w - mu) * inv * gv.w + bt.w;
    ((float4*)(out + (long)row * D))[tid] = ov;
}

// ---------------- launcher ----------------
extern "C" void kernel_launch(void* const* d_in, const int* in_sizes, int n_in,
                              void* d_out, int out_size) {
    const float* x     = (const float*)d_in[0];
    const int*   edge  = (const int*)d_in[1];
    const float* Wq    = (const float*)d_in[2];
    const float* bq    = (const float*)d_in[3];
    const float* Wk    = (const float*)d_in[4];
    const float* bk    = (const float*)d_in[5];
    const float* Wv    = (const float*)d_in[6];
    const float* bv    = (const float*)d_in[7];
    const float* Wo    = (const float*)d_in[8];
    const float* bo    = (const float*)d_in[9];
    const float* gamma = (const float*)d_in[10];
    const float* beta  = (const float*)d_in[11];
    float* out = (float*)d_out;

    float  *pp;
    __half *xh, *ah, *wq, *wk, *wv, *wo;
    cudaGetSymbolAddress((void**)&pp, g_proj);
    cudaGetSymbolAddress((void**)&xh, g_xh);
    cudaGetSymbolAddress((void**)&ah, g_atth);
    cudaGetSymbolAddress((void**)&wq, g_wq);
    cudaGetSymbolAddress((void**)&wk, g_wk);
    cudaGetSymbolAddress((void**)&wv, g_wv);
    cudaGetSymbolAddress((void**)&wo, g_wo);

    cudaFuncSetAttribute(qkv_attn, cudaFuncAttributeMaxDynamicSharedMemorySize, F_SMEM);
    cudaFuncSetAttribute(gemm_fp16, cudaFuncAttributeMaxDynamicSharedMemorySize, GEMM_SMEM);

    // launch 1: mask
    mask_kernel<<<1, 256>>>(edge, in_sizes[1]);

    // launch 2: x -> fp16
    const int XN4 = NROWS * D / 4;
    const int WN4 = D * D / 4;
    round_half<<<(XN4 + 255) / 256, 256>>>(x, xh, XN4);
    // launch 3: all 4 weights -> fp16
    dim3 wgrid((WN4 + 255) / 256, 4);
    round_w4<<<wgrid, 256>>>(Wq, Wk, Wv, Wo, wq, wk, wv, wo, WN4);

    // launch 4: fused QKV GEMM + attention
    dim3 fgrid(H, NROWS / FBM);       // (16, 512) — heads fastest for A reuse in L2
    qkv_attn<<<fgrid, 256, F_SMEM>>>(xh, wq, wk, wv, bq, bk, bv);

    // launch 5: output projection
    dim3 grid1(D / BN, NROWS / BM, 1);
    gemm_fp16<<<grid1, 128, GEMM_SMEM>>>(ah, wo, pp, NROWS, D, D);

    // launch 6: layernorm
    ln_kernel<<<NROWS, 256>>>(x, bo, gamma, beta, out);
}

// round 16
// speedup vs baseline: 1.3332x; 1.3332x over previous
#include <cuda_runtime.h>
#include <cuda_fp16.h>
#include <mma.h>
#include <math.h>
#include <cstdint>

using namespace nvcuda;

#define SEQ 12
#define D 1024
#define H 16
#define HD 64
#define BATCH 4096
#define NROWS (BATCH * SEQ)   // 49152
#define EPS 1e-5f

// ---------------- scratch (no allocations allowed) ----------------
__device__ __half g_qh[NROWS * D];
__device__ __half g_kh[NROWS * D];
__device__ __half g_vh[NROWS * D];
__device__ __half g_projh[NROWS * D];  // h = Wo-proj + bo + x, fp16
__device__ __half g_xh[NROWS * D];     // fp16 x
__device__ __half g_atth[NROWS * D];   // fp16 attention output
__device__ __half g_wq[D * D];         // fp16 weights (original [K,N] layout)
__device__ __half g_wk[D * D];
__device__ __half g_wv[D * D];
__device__ __half g_wo[D * D];
__device__ float  g_mask[SEQ * SEQ];

// ---------------- edge mask (dtype-sniffing: int32 vs int64 payload) ----------------
__global__ void mask_kernel(const int* __restrict__ e32, int n_elems) {
    __shared__ int is64;
    int tid = threadIdx.x;
    if (tid == 0) {
        int all_odd_zero = 1;
        for (int i = 1; i < n_elems; i += 2)
            if (e32[i] != 0) { all_odd_zero = 0; break; }
        is64 = all_odd_zero;
    }
    if (tid < SEQ * SEQ) g_mask[tid] = 0.0f;
    __syncthreads();
    int n_edges = n_elems / 2;
    for (int t = tid; t < n_edges; t += blockDim.x) {
        int r, c;
        if (is64) { r = e32[4 * t]; c = e32[4 * t + 2]; }
        else      { r = e32[2 * t]; c = e32[2 * t + 1]; }
        if (r >= 0 && r < SEQ && c >= 0 && c < SEQ)
            g_mask[r * SEQ + c] = 1.0f;
    }
}

// ---------------- fp32 -> fp16 conversion (vectorized) ----------------
union H2U2 { __half2 h[2]; uint2 u; };

__global__ void __launch_bounds__(256) round_half(const float* __restrict__ in,
                                                  __half* __restrict__ out, int n4) {
    int i = blockIdx.x * blockDim.x + threadIdx.x;
    if (i < n4) {
        float4 v = ((const float4*)in)[i];
        H2U2 t;
        t.h[0] = __floats2half2_rn(v.x, v.y);
        t.h[1] = __floats2half2_rn(v.z, v.w);
        ((uint2*)out)[i] = t.u;
    }
}

__global__ void __launch_bounds__(256) round_w4(const float* __restrict__ w0,
                                                const float* __restrict__ w1,
                                                const float* __restrict__ w2,
                                                const float* __restrict__ w3,
                                                __half* __restrict__ o0,
                                                __half* __restrict__ o1,
                                                __half* __restrict__ o2,
                                                __half* __restrict__ o3, int n4) {
    const float* in; __half* out;
    switch (blockIdx.y) {
        case 0: in = w0; out = o0; break;
        case 1: in = w1; out = o1; break;
        case 2: in = w2; out = o2; break;
        default: in = w3; out = o3; break;
    }
    int i = blockIdx.x * blockDim.x + threadIdx.x;
    if (i < n4) {
        float4 v = ((const float4*)in)[i];
        H2U2 t;
        t.h[0] = __floats2half2_rn(v.x, v.y);
        t.h[1] = __floats2half2_rn(v.z, v.w);
        ((uint2*)out)[i] = t.u;
    }
}

// ---------------- cp.async helpers ----------------
__device__ __forceinline__ void cp16(void* smem_dst, const void* gmem_src) {
    unsigned int d = (unsigned int)__cvta_generic_to_shared(smem_dst);
    asm volatile("cp.async.cg.shared.global [%0], [%1], 16;\n" :: "r"(d), "l"(gmem_src));
}
__device__ __forceinline__ void cp_commit() { asm volatile("cp.async.commit_group;\n"); }
template <int N>
__device__ __forceinline__ void cp_wait() { asm volatile("cp.async.wait_group %0;\n" :: "n"(N)); }

// ---------------- GEMM config (R13/R14-proven: 128 thr, 4 warps, 64x64 tiles) ----------------
#define BM 128
#define BN 128
#define BK 64
#define LDA_H 72
#define LDB_H 136
#define SA_H (BM * LDA_H)
#define SB_H (BK * LDB_H)
#define STAGES 3
#define GEMM_SMEM ((STAGES * (SA_H + SB_H)) * 2)   // 107,520 bytes
#define STG_LD 72

// ---------------- fused QKV GEMM: grid.x packs (col, matrix) for A L2 reuse ----------------
__global__ void __launch_bounds__(128, 2) gemm_qkv(const __half* __restrict__ A,
                                                   const __half* __restrict__ B0,
                                                   const __half* __restrict__ B1,
                                                   const __half* __restrict__ B2,
                                                   __half* __restrict__ C0,
                                                   __half* __restrict__ C1,
                                                   __half* __restrict__ C2) {
    const int mat = blockIdx.x >> 3;          // 0..2 : Q,K,V
    const int bx  = blockIdx.x & 7;           // column block
    const __half* B; __half* C;
    switch (mat) {
        case 0: B = B0; C = C0; break;
        case 1: B = B1; C = C1; break;
        default: B = B2; C = C2; break;
    }

    extern __shared__ __half smh[];
    __half* As = smh;
    __half* Bs = smh + STAGES * SA_H;

    const int tid = threadIdx.x;
    const int wid = tid >> 5;
    const int lane = tid & 31;
    const int wm  = wid >> 1;
    const int wn  = wid & 1;
    const long brow = (long)blockIdx.y * BM;
    const long bcol = (long)bx * BN;

    wmma::fragment<wmma::accumulator, 16, 16, 16, float> acc[4][4];
    #pragma unroll
    for (int m = 0; m < 4; m++)
        #pragma unroll
        for (int n = 0; n < 4; n++)
            wmma::fill_fragment(acc[m][n], 0.0f);

    const int ktiles = D / BK;

    auto issue = [&](int kt, int buf) {
        __half* ad = As + buf * SA_H;
        const __half* Ag = A + brow * D + (long)kt * BK;
        #pragma unroll
        for (int i = 0; i < 8; i++) {
            int idx = tid + i * 128;
            int r  = idx >> 3;
            int c8 = (idx & 7) << 3;
            cp16(ad + r * LDA_H + c8, Ag + (long)r * D + c8);
        }
        __half* bd = Bs + buf * SB_H;
        const __half* Bg = B + (long)kt * BK * D + bcol;
        #pragma unroll
        for (int i = 0; i < 8; i++) {
            int idx = tid + i * 128;
            int r  = idx >> 4;
            int c8 = (idx & 15) << 3;
            cp16(bd + r * LDB_H + c8, Bg + (long)r * D + c8);
        }
    };

    issue(0, 0); cp_commit();
    issue(1, 1); cp_commit();

    for (int kt = 0; kt < ktiles; kt++) {
        cp_wait<1>();
        __syncthreads();

        if (kt + 2 < ktiles) issue(kt + 2, (kt + 2) % STAGES);
        cp_commit();

        const __half* a = As + (kt % STAGES) * SA_H;
        const __half* b = Bs + (kt % STAGES) * SB_H;
        #pragma unroll
        for (int ks = 0; ks < 4; ks++) {
            const int k0 = ks * 16;
            wmma::fragment<wmma::matrix_a, 16, 16, 16, __half, wmma::row_major> af[4];
            wmma::fragment<wmma::matrix_b, 16, 16, 16, __half, wmma::row_major> bf[4];
            #pragma unroll
            for (int m = 0; m < 4; m++)
                wmma::load_matrix_sync(af[m], a + (wm * 64 + m * 16) * LDA_H + k0, LDA_H);
            #pragma unroll
            for (int n = 0; n < 4; n++)
                wmma::load_matrix_sync(bf[n], b + k0 * LDB_H + wn * 64 + n * 16, LDB_H);
            #pragma unroll
            for (int m = 0; m < 4; m++)
                #pragma unroll
                for (int n = 0; n < 4; n++)
                    wmma::mma_sync(acc[m][n], af[m], bf[n], acc[m][n]);
        }
    }

    // fp16 epilogue: stage per-warp fp32 tile in pipeline smem, write half2
    cp_wait<0>();
    __syncthreads();
    float* stage = (float*)smh + wid * (64 * STG_LD);
    #pragma unroll
    for (int m = 0; m < 4; m++)
        #pragma unroll
        for (int n = 0; n < 4; n++)
            wmma::store_matrix_sync(stage + (m * 16) * STG_LD + n * 16, acc[m][n],
                                    STG_LD, wmma::mem_row_major);
    __syncwarp();
    __half* cp = C + (brow + wm * 64) * D + bcol + wn * 64;
    #pragma unroll
    for (int r = 0; r < 64; r++) {
        float lo = stage[r * STG_LD + lane * 2];
        float hi = stage[r * STG_LD + lane * 2 + 1];
        ((__half2*)(cp + (long)r * D))[lane] = __floats2half2_rn(lo, hi);
    }
}

// ---------------- Wo GEMM + bias + residual, fp16 h output ----------------
__global__ void __launch_bounds__(128, 2) gemm_wo(const __half* __restrict__ A,
                                                  const __half* __restrict__ B,
                                                  const float* __restrict__ x,
                                                  const float* __restrict__ bo,
                                                  __half* __restrict__ Ch) {
    extern __shared__ __half smh[];
    __half* As = smh;
    __half* Bs = smh + STAGES * SA_H;

    const int tid = threadIdx.x;
    const int wid = tid >> 5;
    const int lane = tid & 31;
    const int wm  = wid >> 1;
    const int wn  = wid & 1;
    const long brow = (long)blockIdx.y * BM;
    const long bcol = (long)blockIdx.x * BN;

    wmma::fragment<wmma::accumulator, 16, 16, 16, float> acc[4][4];
    #pragma unroll
    for (int m = 0; m < 4; m++)
        #pragma unroll
        for (int n = 0; n < 4; n++)
            wmma::fill_fragment(acc[m][n], 0.0f);

    const int ktiles = D / BK;

    auto issue = [&](int kt, int buf) {
        __half* ad = As + buf * SA_H;
        const __half* Ag = A + brow * D + (long)kt * BK;
        #pragma unroll
        for (int i = 0; i < 8; i++) {
            int idx = tid + i * 128;
            int r  = idx >> 3;
            int c8 = (idx & 7) << 3;
            cp16(ad + r * LDA_H + c8, Ag + (long)r * D + c8);
        }
        __half* bd = Bs + buf * SB_H;
        const __half* Bg = B + (long)kt * BK * D + bcol;
        #pragma unroll
        for (int i = 0; i < 8; i++) {
            int idx = tid + i * 128;
            int r  = idx >> 4;
            int c8 = (idx & 15) << 3;
            cp16(bd + r * LDB_H + c8, Bg + (long)r * D + c8);
        }
    };

    issue(0, 0); cp_commit();
    issue(1, 1); cp_commit();

    for (int kt = 0; kt < ktiles; kt++) {
        cp_wait<1>();
        __syncthreads();

        if (kt + 2 < ktiles) issue(kt + 2, (kt + 2) % STAGES);
        cp_commit();

        const __half* a = As + (kt % STAGES) * SA_H;
        const __half* b = Bs + (kt % STAGES) * SB_H;
        #pragma unroll
        for (int ks = 0; ks < 4; ks++) {
            const int k0 = ks * 16;
            wmma::fragment<wmma::matrix_a, 16, 16, 16, __half, wmma::row_major> af[4];
            wmma::fragment<wmma::matrix_b, 16, 16, 16, __half, wmma::row_major> bf[4];
            #pragma unroll
            for (int m = 0; m < 4; m++)
                wmma::load_matrix_sync(af[m], a + (wm * 64 + m * 16) * LDA_H + k0, LDA_H);
            #pragma unroll
            for (int n = 0; n < 4; n++)
                wmma::load_matrix_sync(bf[n], b + k0 * LDB_H + wn * 64 + n * 16, LDB_H);
            #pragma unroll
            for (int m = 0; m < 4; m++)
                #pragma unroll
                for (int n = 0; n < 4; n++)
                    wmma::mma_sync(acc[m][n], af[m], bf[n], acc[m][n]);
        }
    }

    // epilogue: h = acc + x + bo, write fp16
    cp_wait<0>();
    __syncthreads();
    float* stage = (float*)smh + wid * (64 * STG_LD);
    #pragma unroll
    for (int m = 0; m < 4; m++)
        #pragma unroll
        for (int n = 0; n < 4; n++)
            wmma::store_matrix_sync(stage + (m * 16) * STG_LD + n * 16, acc[m][n],
                                    STG_LD, wmma::mem_row_major);
    __syncwarp();
    const long col0 = bcol + wn * 64;
    const float2 bo2 = ((const float2*)(bo + col0))[lane];
    __half* cp = Ch + (brow + wm * 64) * D + col0;
    const float* xp = x + (brow + wm * 64) * D + col0;
    #pragma unroll
    for (int r = 0; r < 64; r++) {
        float2 xv = ((const float2*)(xp + (long)r * D))[lane];
        float lo = stage[r * STG_LD + lane * 2]     + xv.x + bo2.x;
        float hi = stage[r * STG_LD + lane * 2 + 1] + xv.y + bo2.y;
        ((__half2*)(cp + (long)r * D))[lane] = __floats2half2_rn(lo, hi);
    }
}

// ---------------- warp-per-(b,h) masked attention, no block barriers ----------------
#define AW 4   // warps (bh units) per block
#define LDH 65 // padded stride to break 64-stride bank aliasing

__global__ void __launch_bounds__(AW * 32) attn_kernel(const float* __restrict__ bq,
                                                       const float* __restrict__ bk,
                                                       const float* __restrict__ bv) {
    __shared__ float qs[AW][SEQ][LDH];
    __shared__ float ks[AW][SEQ][LDH];
    __shared__ float vs[AW][SEQ][LDH];
    __shared__ float sc[AW][SEQ][SEQ];

    const int wid = threadIdx.x >> 5;
    const int lane = threadIdx.x & 31;
    const int bh = blockIdx.x * AW + wid;
    const int b = bh >> 4;
    const int h = bh & 15;
    const long base = (long)(b * SEQ) * D + h * HD;

    const float2 bq2 = ((const float2*)(bq + h * HD))[lane];
    const float2 bk2 = ((const float2*)(bk + h * HD))[lane];
    const float2 bv2 = ((const float2*)(bv + h * HD))[lane];

    #pragma unroll
    for (int s = 0; s < SEQ; s++) {
        long off2 = (base + (long)s * D) >> 1;
        float2 q2 = __half22float2(((const __half2*)g_qh)[off2 + lane]);
        float2 k2 = __half22float2(((const __half2*)g_kh)[off2 + lane]);
        float2 v2 = __half22float2(((const __half2*)g_vh)[off2 + lane]);
        qs[wid][s][2 * lane]     = q2.x + bq2.x;
        qs[wid][s][2 * lane + 1] = q2.y + bq2.y;
        ks[wid][s][2 * lane]     = k2.x + bk2.x;
        ks[wid][s][2 * lane + 1] = k2.y + bk2.y;
        vs[wid][s][2 * lane]     = v2.x + bv2.x;
        vs[wid][s][2 * lane + 1] = v2.y + bv2.y;
    }
    __syncwarp();

    #pragma unroll
    for (int it = 0; it < 5; it++) {
        int t = lane + it * 32;
        if (t < SEQ * SEQ) {
            int i = t / SEQ, j = t - (t / SEQ) * SEQ;
            float s = 0.0f;
            #pragma unroll
            for (int d = 0; d < HD; d++) s += qs[wid][i][d] * ks[wid][j][d];
            sc[wid][i][j] = (g_mask[t] == 0.0f) ? -INFINITY : s * 0.125f;
        }
    }
    __syncwarp();

    if (lane < SEQ) {
        float mx = -INFINITY;
        #pragma unroll
        for (int j = 0; j < SEQ; j++) mx = fmaxf(mx, sc[wid][lane][j]);
        float sum = 0.0f;
        #pragma unroll
        for (int j = 0; j < SEQ; j++) {
            float e = __expf(sc[wid][lane][j] - mx);
            sc[wid][lane][j] = e;
            sum += e;
        }
        float inv = 1.0f / sum;
        #pragma unroll
        for (int j = 0; j < SEQ; j++) sc[wid][lane][j] *= inv;
    }
    __syncwarp();

    #pragma unroll
    for (int s = 0; s < SEQ; s++) {
        float a0 = 0.0f, a1 = 0.0f;
        #pragma unroll
        for (int j = 0; j < SEQ; j++) {
            float p = sc[wid][s][j];
            a0 += p * vs[wid][j][2 * lane];
            a1 += p * vs[wid][j][2 * lane + 1];
        }
        ((__half2*)g_atth)[((base + (long)s * D) >> 1) + lane] = __floats2half2_rn(a0, a1);
    }
}

// ---------------- LayerNorm over fp16 h (bias+residual already applied) ----------------
__global__ void __launch_bounds__(256) ln_kernel(const float* __restrict__ gamma,
                                                 const float* __restrict__ beta,
                                                 float* __restrict__ out) {
    const int row = blockIdx.x;
    const int tid = threadIdx.x;
    const int lane = tid & 31, w = tid >> 5;
    __shared__ float rs[8], rq[8];

    uint2 raw = ((const uint2*)(g_projh + (long)row * D))[tid];
    H2U2 u; u.u = raw;
    float2 a = __half22float2(u.h[0]);
    float2 bvv = __half22float2(u.h[1]);
    float hv[4] = {a.x, a.y, bvv.x, bvv.y};

    float sum = hv[0] + hv[1] + hv[2] + hv[3];
    float sq  = hv[0] * hv[0] + hv[1] * hv[1] + hv[2] * hv[2] + hv[3] * hv[3];
    #pragma unroll
    for (int o = 16; o; o >>= 1) {
        sum += __shfl_xor_sync(~0u, sum, o);
        sq  += __shfl_xor_sync(~0u, sq, o);
    }
    if (lane == 0) { rs[w] = sum; rq[w] = sq; }
    __syncthreads();
    if (w == 0) {
        float s = (lane < 8) ? rs[lane] : 0.0f;
        float q = (lane < 8) ? rq[lane] : 0.0f;
        #pragma unroll
        for (int o = 4; o; o >>= 1) {
            s += __shfl_xor_sync(~0u, s, o);
            q += __shfl_xor_sync(~0u, q, o);
        }
        if (lane == 0) { rs[0] = s; rq[0] = q; }
    }
    __syncthreads();
    const float mu  = rs[0] * (1.0f / D);
    const float var = rq[0] * (1.0f / D) - mu * mu;
    const float inv = rsqrtf(var + EPS);

    float4 gv = ((const float4*)gamma)[tid];
    float4 bt = ((const float4*)beta)[tid];
    float4 ov;
    ov.x = (hv[0] - mu) * inv * gv.x + bt.x;
    ov.y = (hv[1] - mu) * inv * gv.y + bt.y;
    ov.z = (hv[2] - mu) * inv * gv.z + bt.z;
    ov.w = (hv[3] - mu) * inv * gv.w + bt.w;
    ((float4*)(out + (long)row * D))[tid] = ov;
}

// ---------------- launcher ----------------
extern "C" void kernel_launch(void* const* d_in, const int* in_sizes, int n_in,
                              void* d_out, int out_size) {
    const float* x     = (const float*)d_in[0];
    const int*   edge  = (const int*)d_in[1];
    const float* Wq    = (const float*)d_in[2];
    const float* bq    = (const float*)d_in[3];
    const float* Wk    = (const float*)d_in[4];
    const float* bk    = (const float*)d_in[5];
    const float* Wv    = (const float*)d_in[6];
    const float* bv    = (const float*)d_in[7];
    const float* Wo    = (const float*)d_in[8];
    const float* bo    = (const float*)d_in[9];
    const float* gamma = (const float*)d_in[10];
    const float* beta  = (const float*)d_in[11];
    float* out = (float*)d_out;

    __half *qh, *kh, *vh, *ph, *xh, *ah, *wq, *wk, *wv, *wo;
    cudaGetSymbolAddress((void**)&qh, g_qh);
    cudaGetSymbolAddress((void**)&kh, g_kh);
    cudaGetSymbolAddress((void**)&vh, g_vh);
    cudaGetSymbolAddress((void**)&ph, g_projh);
    cudaGetSymbolAddress((void**)&xh, g_xh);
    cudaGetSymbolAddress((void**)&ah, g_atth);
    cudaGetSymbolAddress((void**)&wq, g_wq);
    cudaGetSymbolAddress((void**)&wk, g_wk);
    cudaGetSymbolAddress((void**)&wv, g_wv);
    cudaGetSymbolAddress((void**)&wo, g_wo);

    cudaFuncSetAttribute(gemm_qkv, cudaFuncAttributeMaxDynamicSharedMemorySize, GEMM_SMEM);
    cudaFuncSetAttribute(gemm_wo,  cudaFuncAttributeMaxDynamicSharedMemorySize, GEMM_SMEM);

    // launch 1: mask
    mask_kernel<<<1, 256>>>(edge, in_sizes[1]);

    // launch 2: x -> fp16
    const int XN4 = NROWS * D / 4;
    const int WN4 = D * D / 4;
    round_half<<<(XN4 + 255) / 256, 256>>>(x, xh, XN4);
    // launch 3: all 4 weights -> fp16
    dim3 wgrid((WN4 + 255) / 256, 4);
    round_w4<<<wgrid, 256>>>(Wq, Wk, Wv, Wo, wq, wk, wv, wo, WN4);

    // launch 4: fused QKV GEMM (x packs col+matrix -> A read once)
    dim3 qgrid(24, NROWS / BM);       // (24, 384)
    gemm_qkv<<<qgrid, 128, GEMM_SMEM>>>(xh, wq, wk, wv, qh, kh, vh);

    // launch 5: attention
    attn_kernel<<<BATCH * H / AW, AW * 32>>>(bq, bk, bv);

    // launch 6: Wo projection + bias + residual (fp16 h)
    dim3 ogrid(D / BN, NROWS / BM);
    gemm_wo<<<ogrid, 128, GEMM_SMEM>>>(ah, wo, x, bo, ph);

    // launch 7: layernorm
    ln_kernel<<<NROWS, 256>>>(gamma, beta, out);
}

// round 17
// speedup vs baseline: 1.3706x; 1.0280x over previous
#include <cuda_runtime.h>
#include <cuda_fp16.h>
#include <mma.h>
#include <math.h>
#include <cstdint>

using namespace nvcuda;

#define SEQ 12
#define D 1024
#define H 16
#define HD 64
#define BATCH 4096
#define NROWS (BATCH * SEQ)   // 49152
#define EPS 1e-5f

// ---------------- scratch (no allocations allowed) ----------------
__device__ __half g_qh[NROWS * D];
__device__ __half g_kh[NROWS * D];
__device__ __half g_vh[NROWS * D];
__device__ __half g_projh[NROWS * D];  // h = Wo-proj + bo + x, fp16
__device__ __half g_xh[NROWS * D];     // fp16 x
__device__ __half g_atth[NROWS * D];   // fp16 attention output
__device__ __half g_wq[D * D];         // fp16 weights (original [K,N] layout)
__device__ __half g_wk[D * D];
__device__ __half g_wv[D * D];
__device__ __half g_wo[D * D];
__device__ float  g_mask[SEQ * SEQ];

// ---------------- edge mask (dtype-sniffing: int32 vs int64 payload) ----------------
__global__ void mask_kernel(const int* __restrict__ e32, int n_elems) {
    __shared__ int is64;
    int tid = threadIdx.x;
    if (tid == 0) {
        int all_odd_zero = 1;
        for (int i = 1; i < n_elems; i += 2)
            if (e32[i] != 0) { all_odd_zero = 0; break; }
        is64 = all_odd_zero;
    }
    if (tid < SEQ * SEQ) g_mask[tid] = 0.0f;
    __syncthreads();
    int n_edges = n_elems / 2;
    for (int t = tid; t < n_edges; t += blockDim.x) {
        int r, c;
        if (is64) { r = e32[4 * t]; c = e32[4 * t + 2]; }
        else      { r = e32[2 * t]; c = e32[2 * t + 1]; }
        if (r >= 0 && r < SEQ && c >= 0 && c < SEQ)
            g_mask[r * SEQ + c] = 1.0f;
    }
}

// ---------------- fp32 -> fp16 conversion: grid-stride, MLP=4 ----------------
union H2U2 { __half2 h[2]; uint2 u; };

__device__ __forceinline__ uint2 cvt4(float4 v) {
    H2U2 t;
    t.h[0] = __floats2half2_rn(v.x, v.y);
    t.h[1] = __floats2half2_rn(v.z, v.w);
    return t.u;
}

// n4 must be a multiple of 4*gridDim*blockDim chunks handled by the loop; tail handled.
__global__ void __launch_bounds__(256) round_half(const float* __restrict__ in,
                                                  __half* __restrict__ out, int n4) {
    const int stride = gridDim.x * blockDim.x;
    int i = blockIdx.x * blockDim.x + threadIdx.x;
    // main loop: 4 independent float4 per iteration (MLP=4)
    for (; i + 3 * stride < n4; i += 4 * stride) {
        float4 v0 = ((const float4*)in)[i];
        float4 v1 = ((const float4*)in)[i + stride];
        float4 v2 = ((const float4*)in)[i + 2 * stride];
        float4 v3 = ((const float4*)in)[i + 3 * stride];
        ((uint2*)out)[i]              = cvt4(v0);
        ((uint2*)out)[i + stride]     = cvt4(v1);
        ((uint2*)out)[i + 2 * stride] = cvt4(v2);
        ((uint2*)out)[i + 3 * stride] = cvt4(v3);
    }
    for (; i < n4; i += stride)
        ((uint2*)out)[i] = cvt4(((const float4*)in)[i]);
}

__global__ void __launch_bounds__(256) round_w4(const float* __restrict__ w0,
                                                const float* __restrict__ w1,
                                                const float* __restrict__ w2,
                                                const float* __restrict__ w3,
                                                __half* __restrict__ o0,
                                                __half* __restrict__ o1,
                                                __half* __restrict__ o2,
                                                __half* __restrict__ o3, int n4) {
    const float* in; __half* out;
    switch (blockIdx.y) {
        case 0: in = w0; out = o0; break;
        case 1: in = w1; out = o1; break;
        case 2: in = w2; out = o2; break;
        default: in = w3; out = o3; break;
    }
    const int stride = gridDim.x * blockDim.x;
    int i = blockIdx.x * blockDim.x + threadIdx.x;
    for (; i + 3 * stride < n4; i += 4 * stride) {
        float4 v0 = ((const float4*)in)[i];
        float4 v1 = ((const float4*)in)[i + stride];
        float4 v2 = ((const float4*)in)[i + 2 * stride];
        float4 v3 = ((const float4*)in)[i + 3 * stride];
        ((uint2*)out)[i]              = cvt4(v0);
        ((uint2*)out)[i + stride]     = cvt4(v1);
        ((uint2*)out)[i + 2 * stride] = cvt4(v2);
        ((uint2*)out)[i + 3 * stride] = cvt4(v3);
    }
    for (; i < n4; i += stride)
        ((uint2*)out)[i] = cvt4(((const float4*)in)[i]);
}

// ---------------- cp.async helpers ----------------
__device__ __forceinline__ void cp16(void* smem_dst, const void* gmem_src) {
    unsigned int d = (unsigned int)__cvta_generic_to_shared(smem_dst);
    asm volatile("cp.async.cg.shared.global [%0], [%1], 16;\n" :: "r"(d), "l"(gmem_src));
}
__device__ __forceinline__ void cp_commit() { asm volatile("cp.async.commit_group;\n"); }
template <int N>
__device__ __forceinline__ void cp_wait() { asm volatile("cp.async.wait_group %0;\n" :: "n"(N)); }

// ---------------- GEMM config (proven: 128 thr, 4 warps, 64x64 tiles) ----------------
#define BM 128
#define BN 128
#define BK 64
#define LDA_H 72
#define LDB_H 136
#define SA_H (BM * LDA_H)
#define SB_H (BK * LDB_H)
#define STAGES 3
#define GEMM_SMEM ((STAGES * (SA_H + SB_H)) * 2)   // 107,520 bytes
#define STG_LD 72

// ---------------- fused QKV GEMM: grid.x packs (col, matrix) for A L2 reuse ----------------
__global__ void __launch_bounds__(128, 2) gemm_qkv(const __half* __restrict__ A,
                                                   const __half* __restrict__ B0,
                                                   const __half* __restrict__ B1,
                                                   const __half* __restrict__ B2,
                                                   __half* __restrict__ C0,
                                                   __half* __restrict__ C1,
                                                   __half* __restrict__ C2) {
    const int mat = blockIdx.x >> 3;          // 0..2 : Q,K,V
    const int bx  = blockIdx.x & 7;           // column block
    const __half* B; __half* C;
    switch (mat) {
        case 0: B = B0; C = C0; break;
        case 1: B = B1; C = C1; break;
        default: B = B2; C = C2; break;
    }

    extern __shared__ __half smh[];
    __half* As = smh;
    __half* Bs = smh + STAGES * SA_H;

    const int tid = threadIdx.x;
    const int wid = tid >> 5;
    const int lane = tid & 31;
    const int wm  = wid >> 1;
    const int wn  = wid & 1;
    const long brow = (long)blockIdx.y * BM;
    const long bcol = (long)bx * BN;

    wmma::fragment<wmma::accumulator, 16, 16, 16, float> acc[4][4];
    #pragma unroll
    for (int m = 0; m < 4; m++)
        #pragma unroll
        for (int n = 0; n < 4; n++)
            wmma::fill_fragment(acc[m][n], 0.0f);

    const int ktiles = D / BK;

    auto issue = [&](int kt, int buf) {
        __half* ad = As + buf * SA_H;
        const __half* Ag = A + brow * D + (long)kt * BK;
        #pragma unroll
        for (int i = 0; i < 8; i++) {
            int idx = tid + i * 128;
            int r  = idx >> 3;
            int c8 = (idx & 7) << 3;
            cp16(ad + r * LDA_H + c8, Ag + (long)r * D + c8);
        }
        __half* bd = Bs + buf * SB_H;
        const __half* Bg = B + (long)kt * BK * D + bcol;
        #pragma unroll
        for (int i = 0; i < 8; i++) {
            int idx = tid + i * 128;
            int r  = idx >> 4;
            int c8 = (idx & 15) << 3;
            cp16(bd + r * LDB_H + c8, Bg + (long)r * D + c8);
        }
    };

    issue(0, 0); cp_commit();
    issue(1, 1); cp_commit();

    for (int kt = 0; kt < ktiles; kt++) {
        cp_wait<1>();
        __syncthreads();

        if (kt + 2 < ktiles) issue(kt + 2, (kt + 2) % STAGES);
        cp_commit();

        const __half* a = As + (kt % STAGES) * SA_H;
        const __half* b = Bs + (kt % STAGES) * SB_H;
        #pragma unroll
        for (int ks = 0; ks < 4; ks++) {
            const int k0 = ks * 16;
            wmma::fragment<wmma::matrix_a, 16, 16, 16, __half, wmma::row_major> af[4];
            wmma::fragment<wmma::matrix_b, 16, 16, 16, __half, wmma::row_major> bf[4];
            #pragma unroll
            for (int m = 0; m < 4; m++)
                wmma::load_matrix_sync(af[m], a + (wm * 64 + m * 16) * LDA_H + k0, LDA_H);
            #pragma unroll
            for (int n = 0; n < 4; n++)
                wmma::load_matrix_sync(bf[n], b + k0 * LDB_H + wn * 64 + n * 16, LDB_H);
            #pragma unroll
            for (int m = 0; m < 4; m++)
                #pragma unroll
                for (int n = 0; n < 4; n++)
                    wmma::mma_sync(acc[m][n], af[m], bf[n], acc[m][n]);
        }
    }

    cp_wait<0>();
    __syncthreads();
    float* stage = (float*)smh + wid * (64 * STG_LD);
    #pragma unroll
    for (int m = 0; m < 4; m++)
        #pragma unroll
        for (int n = 0; n < 4; n++)
            wmma::store_matrix_sync(stage + (m * 16) * STG_LD + n * 16, acc[m][n],
                                    STG_LD, wmma::mem_row_major);
    __syncwarp();
    __half* cp = C + (brow + wm * 64) * D + bcol + wn * 64;
    #pragma unroll
    for (int r = 0; r < 64; r++) {
        float lo = stage[r * STG_LD + lane * 2];
        float hi = stage[r * STG_LD + lane * 2 + 1];
        ((__half2*)(cp + (long)r * D))[lane] = __floats2half2_rn(lo, hi);
    }
}

// ---------------- Wo GEMM + bias + residual, fp16 h output ----------------
__global__ void __launch_bounds__(128, 2) gemm_wo(const __half* __restrict__ A,
                                                  const __half* __restrict__ B,
                                                  const float* __restrict__ x,
                                                  const float* __restrict__ bo,
                                                  __half* __restrict__ Ch) {
    extern __shared__ __half smh[];
    __half* As = smh;
    __half* Bs = smh + STAGES * SA_H;

    const int tid = threadIdx.x;
    const int wid = tid >> 5;
    const int lane = tid & 31;
    const int wm  = wid >> 1;
    const int wn  = wid & 1;
    const long brow = (long)blockIdx.y * BM;
    const long bcol = (long)blockIdx.x * BN;

    wmma::fragment<wmma::accumulator, 16, 16, 16, float> acc[4][4];
    #pragma unroll
    for (int m = 0; m < 4; m++)
        #pragma unroll
        for (int n = 0; n < 4; n++)
            wmma::fill_fragment(acc[m][n], 0.0f);

    const int ktiles = D / BK;

    auto issue = [&](int kt, int buf) {
        __half* ad = As + buf * SA_H;
        const __half* Ag = A + brow * D + (long)kt * BK;
        #pragma unroll
        for (int i = 0; i < 8; i++) {
            int idx = tid + i * 128;
            int r  = idx >> 3;
            int c8 = (idx & 7) << 3;
            cp16(ad + r * LDA_H + c8, Ag + (long)r * D + c8);
        }
        __half* bd = Bs + buf * SB_H;
        const __half* Bg = B + (long)kt * BK * D + bcol;
        #pragma unroll
        for (int i = 0; i < 8; i++) {
            int idx = tid + i * 128;
            int r  = idx >> 4;
            int c8 = (idx & 15) << 3;
            cp16(bd + r * LDB_H + c8, Bg + (long)r * D + c8);
        }
    };

    issue(0, 0); cp_commit();
    issue(1, 1); cp_commit();

    for (int kt = 0; kt < ktiles; kt++) {
        cp_wait<1>();
        __syncthreads();

        if (kt + 2 < ktiles) issue(kt + 2, (kt + 2) % STAGES);
        cp_commit();

        const __half* a = As + (kt % STAGES) * SA_H;
        const __half* b = Bs + (kt % STAGES) * SB_H;
        #pragma unroll
        for (int ks = 0; ks < 4; ks++) {
            const int k0 = ks * 16;
            wmma::fragment<wmma::matrix_a, 16, 16, 16, __half, wmma::row_major> af[4];
            wmma::fragment<wmma::matrix_b, 16, 16, 16, __half, wmma::row_major> bf[4];
            #pragma unroll
            for (int m = 0; m < 4; m++)
                wmma::load_matrix_sync(af[m], a + (wm * 64 + m * 16) * LDA_H + k0, LDA_H);
            #pragma unroll
            for (int n = 0; n < 4; n++)
                wmma::load_matrix_sync(bf[n], b + k0 * LDB_H + wn * 64 + n * 16, LDB_H);
            #pragma unroll
            for (int m = 0; m < 4; m++)
                #pragma unroll
                for (int n = 0; n < 4; n++)
                    wmma::mma_sync(acc[m][n], af[m], bf[n], acc[m][n]);
        }
    }

    cp_wait<0>();
    __syncthreads();
    float* stage = (float*)smh + wid * (64 * STG_LD);
    #pragma unroll
    for (int m = 0; m < 4; m++)
        #pragma unroll
        for (int n = 0; n < 4; n++)
            wmma::store_matrix_sync(stage + (m * 16) * STG_LD + n * 16, acc[m][n],
                                    STG_LD, wmma::mem_row_major);
    __syncwarp();
    const long col0 = bcol + wn * 64;
    const float2 bo2 = ((const float2*)(bo + col0))[lane];
    __half* cp = Ch + (brow + wm * 64) * D + col0;
    const float* xp = x + (brow + wm * 64) * D + col0;
    #pragma unroll
    for (int r = 0; r < 64; r++) {
        float2 xv = ((const float2*)(xp + (long)r * D))[lane];
        float lo = stage[r * STG_LD + lane * 2]     + xv.x + bo2.x;
        float hi = stage[r * STG_LD + lane * 2 + 1] + xv.y + bo2.y;
        ((__half2*)(cp + (long)r * D))[lane] = __floats2half2_rn(lo, hi);
    }
}

// ---------------- warp-per-(b,h) masked attention, vectorized smem reads ----------------
#define AW 4   // warps (bh units) per block
#define LDH 68 // padded stride (multiple of 4 for float4 reads, 68%32=4 breaks aliasing)

__global__ void __launch_bounds__(AW * 32) attn_kernel(const float* __restrict__ bq,
                                                       const float* __restrict__ bk,
                                                       const float* __restrict__ bv) {
    __shared__ float qs[AW][SEQ][LDH];
    __shared__ float ks[AW][SEQ][LDH];
    __shared__ float vs[AW][SEQ][LDH];
    __shared__ float sc[AW][SEQ][SEQ];

    const int wid = threadIdx.x >> 5;
    const int lane = threadIdx.x & 31;
    const int bh = blockIdx.x * AW + wid;
    const int b = bh >> 4;
    const int h = bh & 15;
    const long base = (long)(b * SEQ) * D + h * HD;

    const float2 bq2 = ((const float2*)(bq + h * HD))[lane];
    const float2 bk2 = ((const float2*)(bk + h * HD))[lane];
    const float2 bv2 = ((const float2*)(bv + h * HD))[lane];

    #pragma unroll
    for (int s = 0; s < SEQ; s++) {
        long off2 = (base + (long)s * D) >> 1;
        float2 q2 = __half22float2(((const __half2*)g_qh)[off2 + lane]);
        float2 k2 = __half22float2(((const __half2*)g_kh)[off2 + lane]);
        float2 v2 = __half22float2(((const __half2*)g_vh)[off2 + lane]);
        qs[wid][s][2 * lane]     = q2.x + bq2.x;
        qs[wid][s][2 * lane + 1] = q2.y + bq2.y;
        ks[wid][s][2 * lane]     = k2.x + bk2.x;
        ks[wid][s][2 * lane + 1] = k2.y + bk2.y;
        vs[wid][s][2 * lane]     = v2.x + bv2.x;
        vs[wid][s][2 * lane + 1] = v2.y + bv2.y;
    }
    __syncwarp();

    // scores: float4 smem reads (LDS.128), 16 iters of 4-wide FMA
    #pragma unroll
    for (int it = 0; it < 5; it++) {
        int t = lane + it * 32;
        if (t < SEQ * SEQ) {
            int i = t / SEQ, j = t - (t / SEQ) * SEQ;
            const float4* qr = (const float4*)qs[wid][i];
            const float4* kr = (const float4*)ks[wid][j];
            float s = 0.0f;
            #pragma unroll
            for (int d4 = 0; d4 < 16; d4++) {
                float4 q = qr[d4];
                float4 k = kr[d4];
                s += q.x * k.x + q.y * k.y + q.z * k.z + q.w * k.w;
            }
            sc[wid][i][j] = (g_mask[t] == 0.0f) ? -INFINITY : s * 0.125f;
        }
    }
    __syncwarp();

    if (lane < SEQ) {
        float mx = -INFINITY;
        #pragma unroll
        for (int j = 0; j < SEQ; j++) mx = fmaxf(mx, sc[wid][lane][j]);
        float sum = 0.0f;
        #pragma unroll
        for (int j = 0; j < SEQ; j++) {
            float e = __expf(sc[wid][lane][j] - mx);
            sc[wid][lane][j] = e;
            sum += e;
        }
        float inv = 1.0f / sum;
        #pragma unroll
        for (int j = 0; j < SEQ; j++) sc[wid][lane][j] *= inv;
    }
    __syncwarp();

    // AV: float2 smem reads
    #pragma unroll
    for (int s = 0; s < SEQ; s++) {
        float a0 = 0.0f, a1 = 0.0f;
        #pragma unroll
        for (int j = 0; j < SEQ; j++) {
            float p = sc[wid][s][j];
            float2 v = *(const float2*)&vs[wid][j][2 * lane];
            a0 += p * v.x;
            a1 += p * v.y;
        }
        ((__half2*)g_atth)[((base + (long)s * D) >> 1) + lane] = __floats2half2_rn(a0, a1);
    }
}

// ---------------- LayerNorm over fp16 h (bias+residual already applied) ----------------
__global__ void __launch_bounds__(256) ln_kernel(const float* __restrict__ gamma,
                                                 const float* __restrict__ beta,
                                                 float* __restrict__ out) {
    const int row = blockIdx.x;
    const int tid = threadIdx.x;
    const int lane = tid & 31, w = tid >> 5;
    __shared__ float rs[8], rq[8];

    uint2 raw = ((const uint2*)(g_projh + (long)row * D))[tid];
    H2U2 u; u.u = raw;
    float2 a = __half22float2(u.h[0]);
    float2 bvv = __half22float2(u.h[1]);
    float hv[4] = {a.x, a.y, bvv.x, bvv.y};

    float sum = hv[0] + hv[1] + hv[2] + hv[3];
    float sq  = hv[0] * hv[0] + hv[1] * hv[1] + hv[2] * hv[2] + hv[3] * hv[3];
    #pragma unroll
    for (int o = 16; o; o >>= 1) {
        sum += __shfl_xor_sync(~0u, sum, o);
        sq  += __shfl_xor_sync(~0u, sq, o);
    }
    if (lane == 0) { rs[w] = sum; rq[w] = sq; }
    __syncthreads();
    if (w == 0) {
        float s = (lane < 8) ? rs[lane] : 0.0f;
        float q = (lane < 8) ? rq[lane] : 0.0f;
        #pragma unroll
        for (int o = 4; o; o >>= 1) {
            s += __shfl_xor_sync(~0u, s, o);
            q += __shfl_xor_sync(~0u, q, o);
        }
        if (lane == 0) { rs[0] = s; rq[0] = q; }
    }
    __syncthreads();
    const float mu  = rs[0] * (1.0f / D);
    const float var = rq[0] * (1.0f / D) - mu * mu;
    const float inv = rsqrtf(var + EPS);

    float4 gv = ((const float4*)gamma)[tid];
    float4 bt = ((const float4*)beta)[tid];
    float4 ov;
    ov.x = (hv[0] - mu) * inv * gv.x + bt.x;
    ov.y = (hv[1] - mu) * inv * gv.y + bt.y;
    ov.z = (hv[2] - mu) * inv * gv.z + bt.z;
    ov.w = (hv[3] - mu) * inv * gv.w + bt.w;
    ((float4*)(out + (long)row * D))[tid] = ov;
}

// ---------------- launcher ----------------
extern "C" void kernel_launch(void* const* d_in, const int* in_sizes, int n_in,
                              void* d_out, int out_size) {
    const float* x     = (const float*)d_in[0];
    const int*   edge  = (const int*)d_in[1];
    const float* Wq    = (const float*)d_in[2];
    const float* bq    = (const float*)d_in[3];
    const float* Wk    = (const float*)d_in[4];
    const float* bk    = (const float*)d_in[5];
    const float* Wv    = (const float*)d_in[6];
    const float* bv    = (const float*)d_in[7];
    const float* Wo    = (const float*)d_in[8];
    const float* bo    = (const float*)d_in[9];
    const float* gamma = (const float*)d_in[10];
    const float* beta  = (const float*)d_in[11];
    float* out = (float*)d_out;

    __half *qh, *kh, *vh, *ph, *xh, *ah, *wq, *wk, *wv, *wo;
    cudaGetSymbolAddress((void**)&qh, g_qh);
    cudaGetSymbolAddress((void**)&kh, g_kh);
    cudaGetSymbolAddress((void**)&vh, g_vh);
    cudaGetSymbolAddress((void**)&ph, g_projh);
    cudaGetSymbolAddress((void**)&xh, g_xh);
    cudaGetSymbolAddress((void**)&ah, g_atth);
    cudaGetSymbolAddress((void**)&wq, g_wq);
    cudaGetSymbolAddress((void**)&wk, g_wk);
    cudaGetSymbolAddress((void**)&wv, g_wv);
    cudaGetSymbolAddress((void**)&wo, g_wo);

    cudaFuncSetAttribute(gemm_qkv, cudaFuncAttributeMaxDynamicSharedMemorySize, GEMM_SMEM);
    cudaFuncSetAttribute(gemm_wo,  cudaFuncAttributeMaxDynamicSharedMemorySize, GEMM_SMEM);

    // launch 1: mask
    mask_kernel<<<1, 256>>>(edge, in_sizes[1]);

    // launch 2: x -> fp16 (grid-stride, MLP=4; 1184 blocks = 8 blocks/SM)
    const int XN4 = NROWS * D / 4;
    const int WN4 = D * D / 4;
    round_half<<<1184, 256>>>(x, xh, XN4);
    // launch 3: weights -> fp16 (grid-stride, MLP=4)
    dim3 wgrid(256, 4);
    round_w4<<<wgrid, 256>>>(Wq, Wk, Wv, Wo, wq, wk, wv, wo, WN4);

    // launch 4: fused QKV GEMM (x packs col+matrix -> A read once)
    dim3 qgrid(24, NROWS / BM);       // (24, 384)
    gemm_qkv<<<qgrid, 128, GEMM_SMEM>>>(xh, wq, wk, wv, qh, kh, vh);

    // launch 5: attention
    attn_kernel<<<BATCH * H / AW, AW * 32>>>(bq, bk, bv);

    // launch 6: Wo projection + bias + residual (fp16 h)
    dim3 ogrid(D / BN, NROWS / BM);
    gemm_wo<<<ogrid, 128, GEMM_SMEM>>>(ah, wo, x, bo, ph);

    // launch 7: layernorm
    ln_kernel<<<NROWS, 256>>>(gamma, beta, out);
}